// round 3
// baseline (speedup 1.0000x reference)
#include <cuda_runtime.h>
#include <cstdint>

#define OUT_F 28672
#define IN_F  8192
#define ROW_INTS  (IN_F / 2)        // 4096 int32 byte-values per row
#define ROW_UINT4 (ROW_INTS / 4)    // 1024 uint4 per row
#define RPB 32                      // rows per block
#define NW  8                       // warps per block
#define SP_STRIDE 33                // padded stride for s_part (bank-conflict-free)

// qweight is int32 (harness widens uint8): each element holds one byte value,
// two 4-bit codes (lo nibble = even col, hi nibble = odd col).
// Warp w owns ints [512w, 512w+512) of every row, processed in 4 quarter
// passes h. In pass h, lane l loads the uint4 at index 128w+32h+l of each row
// -> ints 4*(128w+32h+l)..+3 -> columns 1024w+256h+8l..+7 (8 x-floats in regs).

__global__ __launch_bounds__(256, 7)
void q3_matvec_kernel(const float* __restrict__ x,
                      const int* __restrict__ qw,
                      const float* __restrict__ kv,
                      const float* __restrict__ bias,
                      float* __restrict__ y)
{
    __shared__ float s_lut[RPB * 16];          // 32 row-LUTs, conflict-free
    __shared__ float s_part[32 * SP_STRIDE];   // [j = w*4+g][r], padded

    const int t = threadIdx.x;
    const int w = t >> 5;
    const int l = t & 31;
    const int row0 = blockIdx.x * RPB;

    // Stage 32 row-LUTs (512 floats = 256 float2).
    {
        const float2* kvp = reinterpret_cast<const float2*>(kv + (size_t)row0 * 16);
        reinterpret_cast<float2*>(s_lut)[t] = kvp[t];
    }
    // Zero partials: 1056 floats / 256 threads.
    s_part[t] = 0.f;
    s_part[t + 256] = 0.f;
    s_part[t + 512] = 0.f;
    s_part[t + 768] = 0.f;
    if (t < 32 * SP_STRIDE - 1024) s_part[t + 1024] = 0.f;
    __syncthreads();

    const int g = l >> 3;                        // octet id within warp
    const int jrow = (w * 4 + g) * SP_STRIDE;    // s_part row for this octet

    #pragma unroll 1
    for (int h = 0; h < 4; h++) {
        // x for this pass: 8 consecutive floats per lane, in registers.
        const float4* xp = reinterpret_cast<const float4*>(
            x + (w << 10) + (h << 8) + (l << 3));
        const float4 xa = xp[0];
        const float4 xb = xp[1];

        const uint4* qp = reinterpret_cast<const uint4*>(qw)
                        + (size_t)row0 * ROW_UINT4 + (w << 7) + (h << 5) + l;

        uint4 q = qp[0];   // prefetch row 0

        #pragma unroll 4
        for (int r = 0; r < RPB; r++) {
            // Prefetch next row (wraps to row 0 on last iter: L2 hit, harmless).
            uint4 qn = qp[(size_t)((r + 1) & (RPB - 1)) * ROW_UINT4];

            const float* lut = s_lut + r * 16;
            float a0 = 0.f, a1 = 0.f;
            a0 = fmaf(lut[q.x & 15u],        xa.x, a0);
            a1 = fmaf(lut[(q.x >> 4) & 15u], xa.y, a1);
            a0 = fmaf(lut[q.y & 15u],        xa.z, a0);
            a1 = fmaf(lut[(q.y >> 4) & 15u], xa.w, a1);
            a0 = fmaf(lut[q.z & 15u],        xb.x, a0);
            a1 = fmaf(lut[(q.z >> 4) & 15u], xb.y, a1);
            a0 = fmaf(lut[q.w & 15u],        xb.z, a0);
            a1 = fmaf(lut[(q.w >> 4) & 15u], xb.w, a1);
            q = qn;

            // Reduce within each 8-lane octet (3 levels), then one lane per
            // octet accumulates into s_part. No cross-warp race (w in index).
            float acc = a0 + a1;
            acc += __shfl_xor_sync(0xffffffffu, acc, 1);
            acc += __shfl_xor_sync(0xffffffffu, acc, 2);
            acc += __shfl_xor_sync(0xffffffffu, acc, 4);
            if ((l & 7) == 0) s_part[jrow + r] += acc;
        }
    }
    __syncthreads();

    // Final: 32 partials per row, conflict-free (stride-33 padding).
    if (t < RPB) {
        float s = 0.f;
        #pragma unroll
        for (int j = 0; j < 32; j++) s += s_part[j * SP_STRIDE + t];
        y[row0 + t] = s + bias[row0 + t];
    }
}

extern "C" void kernel_launch(void* const* d_in, const int* in_sizes, int n_in,
                              void* d_out, int out_size)
{
    const float* x    = (const float*)d_in[0];
    const int*   qw   = (const int*)d_in[1];
    const float* kv   = (const float*)d_in[2];
    const float* bias = (const float*)d_in[3];
    float*       y    = (float*)d_out;

    dim3 grid(OUT_F / RPB);   // 896 blocks, all resident in one wave at 7/SM
    dim3 block(256);
    q3_matvec_kernel<<<grid, block>>>(x, qw, kv, bias, y);
}